// round 8
// baseline (speedup 1.0000x reference)
#include <cuda_runtime.h>
#include <math.h>
#include <float.h>

#define NROWS 32768
#define FIN   1024
#define FOUT  512

#define NB     296                 // main blocks = 148 SMs * 2 (exact single wave)
#define TPB    256
#define WARPS  8
#define MAXRPB 112                 // max rows per block (111 actual)
#define UP     16                  // u-combine partial blocks
#define OUTB   64                  // blocks for W1 matvec partials

// ---- scratch (allocation-free: device globals) ----
__device__ __align__(16) float  g_v[FIN];          // W @ a2 (fp32, hot loop)
__device__ double g_hwa1[FIN];                     // h[j] * (W@a1)[j]
__device__ double g_c1;                            // (h@W)·a1
__device__ double g_scores[NROWS];                 // leaky_relu scores (double)
__device__ float  g_bm[NB];                        // per-block running max
__device__ double g_zp[NB];                        // per-block Z partials
__device__ __align__(16) float g_bu[NB * FIN];     // per-block weighted adj sums
__device__ __align__(16) float g_up[UP * FIN];     // chunk partials of u
__device__ float  g_um[UP];                        // chunk-local max shifts
__device__ double g_thresh;                        // log(Z) - log(N)
__device__ __align__(16) float g_u[FIN];           // attention @ adj
__device__ float  g_op[OUTB * FOUT];               // out partials

// ==== double-float (TwoSum) helpers — all FP32 pipe ====
__device__ __forceinline__ void df_add_f(float& hi, float& lo, float b) {
    float s = hi + b;
    float v = s - hi;
    float e = (hi - (s - v)) + (b - v);
    lo += e;
    hi = s;
}
__device__ __forceinline__ void df_renorm(float& hi, float& lo) {
    float t = hi + lo;
    lo = lo - (t - hi);
    hi = t;
}
__device__ __forceinline__ void df_add_df(float& hi, float& lo, float bh, float bl) {
    float s = hi + bh;
    float v = s - hi;
    float e = (hi - (s - v)) + (bh - v);
    e += lo + bl;
    float t = s + e;
    lo = e - (t - s);
    hi = t;
}

// ---- 1. v = W@a2 (double->fp32) ; hwa1[j] = h[j]*(W@a1)[j] (double) ----
__global__ void prep_kernel(const float* __restrict__ W,
                            const float* __restrict__ a,
                            const float* __restrict__ h) {
    __shared__ double r1[128], r2[128];
    int j = blockIdx.x, t = threadIdx.x;
    const float* Wr = W + (size_t)j * FOUT;
    double d1 = 0.0, d2 = 0.0;
    #pragma unroll
    for (int k = t; k < FOUT; k += 128) {
        double w = (double)Wr[k];
        d1 += w * (double)a[k];
        d2 += w * (double)a[FOUT + k];
    }
    r1[t] = d1; r2[t] = d2;
    __syncthreads();
    for (int s = 64; s > 0; s >>= 1) {
        if (t < s) { r1[t] += r1[t + s]; r2[t] += r2[t + s]; }
        __syncthreads();
    }
    if (t == 0) {
        g_v[j]    = (float)r2[0];
        g_hwa1[j] = (double)h[j] * r1[0];
    }
}

// ---- 2. c1 = sum(hwa1) (double) ----
__global__ void c1_kernel() {
    __shared__ double red[256];
    int t = threadIdx.x;
    red[t] = g_hwa1[t] + g_hwa1[t + 256] + g_hwa1[t + 512] + g_hwa1[t + 768];
    __syncthreads();
    for (int s = 128; s > 0; s >>= 1) {
        if (t < s) red[t] += red[t + s];
        __syncthreads();
    }
    if (t == 0) g_c1 = red[0];
}

// ---- 3. fused main pass over adj: scores + weighted sums + per-block Z partial ----
__global__ __launch_bounds__(TPB, 2) void main_kernel(const float* __restrict__ adj) {
    __shared__ float4 sv4[FIN / 4];
    __shared__ float4 su4[WARPS * (FIN / 4)];
    __shared__ double s_sc[MAXRPB];
    __shared__ float s_m[WARPS], s_f[WARPS];
    __shared__ double s_zr[TPB];

    int tid  = threadIdx.x;
    int w    = tid >> 5;
    int lane = tid & 31;

    sv4[tid] = ((const float4*)g_v)[tid];
    __syncthreads();
    double c1d = g_c1;
    float c1h = (float)c1d;
    float c1l = (float)(c1d - (double)c1h);

    int start = (blockIdx.x * NROWS) / NB;
    int end   = ((blockIdx.x + 1) * NROWS) / NB;
    int len   = end - start;                    // 110 or 111
    int cnt   = (len - w + 7) / 8;              // rows for this warp (13/14)

    float acc[32];
    #pragma unroll
    for (int i = 0; i < 32; i++) acc[i] = 0.f;
    float m = -FLT_MAX;

    const int RSTRIDE = 8 * (FIN / 4);          // 8 rows in float4 units
    const float4* base = (const float4*)adj + (size_t)(start + w) * (FIN / 4) + lane;

    #pragma unroll 1
    for (int i = 0; i < cnt; i++) {
        const float4* rp = base + (size_t)i * RSTRIDE;
        float4 rv[8];
        #pragma unroll
        for (int c = 0; c < 8; c++) rv[c] = rp[c * 32];   // 8 batched LDG.128

        // df-precision dot (FP32 pipe only)
        float dh = 0.f, dl = 0.f;
        #pragma unroll
        for (int c = 0; c < 8; c++) {
            float4 vv = sv4[c * 32 + lane];
            float cd = rv[c].x * vv.x;
            cd = fmaf(rv[c].y, vv.y, cd);
            cd = fmaf(rv[c].z, vv.z, cd);
            cd = fmaf(rv[c].w, vv.w, cd);
            df_add_f(dh, dl, cd);
        }
        df_renorm(dh, dl);
        #pragma unroll
        for (int off = 16; off > 0; off >>= 1) {
            float oh = __shfl_xor_sync(0xffffffffu, dh, off);
            float ol = __shfl_xor_sync(0xffffffffu, dl, off);
            df_add_df(dh, dl, oh, ol);
        }
        df_add_df(dh, dl, c1h, c1l);

        // leaky relu on the df pair
        if (dh < 0.f) {
            float ph = dh * 0.1f;
            float pl = fmaf(dh, 0.1f, -ph);
            pl = fmaf(dl, 0.1f, pl);
            float t = ph + pl;
            dl = pl - (t - ph);
            dh = t;
        }

        if (lane == 0) {
            double sc = (double)dh + (double)dl;   // only FP64 in hot loop
            g_scores[start + w + i * 8] = sc;
            s_sc[w + i * 8] = sc;
        }

        float sf = dh;
        if (sf > m) {                              // uniform branch, rare
            float f = expf(m - sf);                // first hit: exp(-inf)=0
            #pragma unroll
            for (int k = 0; k < 32; k++) acc[k] *= f;
            m = sf;
        }
        float wt = expf(sf - m);
        #pragma unroll
        for (int c = 0; c < 8; c++) {
            acc[c * 4 + 0] = fmaf(wt, rv[c].x, acc[c * 4 + 0]);
            acc[c * 4 + 1] = fmaf(wt, rv[c].y, acc[c * 4 + 1]);
            acc[c * 4 + 2] = fmaf(wt, rv[c].z, acc[c * 4 + 2]);
            acc[c * 4 + 3] = fmaf(wt, rv[c].w, acc[c * 4 + 3]);
        }
    }

    if (lane == 0) s_m[w] = m;
    #pragma unroll
    for (int c = 0; c < 8; c++)
        su4[w * (FIN / 4) + c * 32 + lane] =
            make_float4(acc[c * 4], acc[c * 4 + 1], acc[c * 4 + 2], acc[c * 4 + 3]);
    __syncthreads();

    float mb = s_m[0];
    #pragma unroll
    for (int ww = 1; ww < WARPS; ww++) mb = fmaxf(mb, s_m[ww]);
    if (tid < WARPS) s_f[tid] = expf(s_m[tid] - mb);
    __syncthreads();

    float4 us = make_float4(0.f, 0.f, 0.f, 0.f);
    #pragma unroll
    for (int ww = 0; ww < WARPS; ww++) {
        float f = s_f[ww];
        float4 v = su4[ww * (FIN / 4) + tid];
        us.x = fmaf(f, v.x, us.x); us.y = fmaf(f, v.y, us.y);
        us.z = fmaf(f, v.z, us.z); us.w = fmaf(f, v.w, us.w);
    }
    ((float4*)g_bu)[blockIdx.x * (FIN / 4) + tid] = us;
    if (tid == 0) g_bm[blockIdx.x] = mb;

    // per-block Z partial: exp(sc) with first-order double residual correction
    double zt = 0.0;
    if (tid < len) {
        double sc = s_sc[tid];
        float sf = (float)sc;
        double delta = sc - (double)sf;
        zt = (double)expf(sf) * (1.0 + delta);
    }
    s_zr[tid] = zt;
    __syncthreads();
    for (int s = 128; s > 0; s >>= 1) {
        if (tid < s) s_zr[tid] += s_zr[tid + s];
        __syncthreads();
    }
    if (tid == 0) g_zp[blockIdx.x] = s_zr[0];
}

// ---- 4. u partials: coalesced scan of g_bu rows, chunk-local max shift ----
__global__ void upartial_kernel() {
    int t = threadIdx.x;       // 0..255 = float4 column (coalesced)
    int p = blockIdx.x;        // 0..UP-1
    int b0 = (p * NB) / UP, b1 = ((p + 1) * NB) / UP;

    float Mp = -FLT_MAX;
    for (int b = b0; b < b1; b++) Mp = fmaxf(Mp, g_bm[b]);

    float4 us = make_float4(0.f, 0.f, 0.f, 0.f);
    for (int b = b0; b < b1; b++) {
        float f = expf(g_bm[b] - Mp);
        float4 v = ((const float4*)g_bu)[(size_t)b * (FIN / 4) + t];
        us.x = fmaf(f, v.x, us.x); us.y = fmaf(f, v.y, us.y);
        us.z = fmaf(f, v.z, us.z); us.w = fmaf(f, v.w, us.w);
    }
    ((float4*)g_up)[p * (FIN / 4) + t] = us;
    if (t == 0) g_um[p] = Mp;
}

// ---- 5. u final: Z reduce, threshold, combine chunk partials ----
__global__ void ufinal_kernel() {
    __shared__ double zred[256];
    int t = threadIdx.x;

    double z = 0.0;
    for (int b = t; b < NB; b += 256) z += g_zp[b];
    zred[t] = z;
    __syncthreads();
    for (int s = 128; s > 0; s >>= 1) {
        if (t < s) zred[t] += zred[t + s];
        __syncthreads();
    }
    double Z = zred[0];
    if (t == 0) g_thresh = log(Z) - log((double)NROWS);

    float4 us = make_float4(0.f, 0.f, 0.f, 0.f);
    #pragma unroll
    for (int p = 0; p < UP; p++) {
        float f = (float)(exp((double)g_um[p]) / Z);
        float4 v = ((const float4*)g_up)[p * (FIN / 4) + t];
        us.x = fmaf(f, v.x, us.x); us.y = fmaf(f, v.y, us.y);
        us.z = fmaf(f, v.z, us.z); us.w = fmaf(f, v.w, us.w);
    }
    ((float4*)g_u)[t] = us;
}

// ---- 6. out partials: u @ W_1, j-split across 64 blocks ----
__global__ void out_partial_kernel(const float* __restrict__ W1) {
    int k = threadIdx.x;   // 0..511 coalesced over W1 columns
    int b = blockIdx.x;    // 0..63
    float s = 0.f;
    #pragma unroll
    for (int jj = 0; jj < FIN / OUTB; jj++) {
        int j = b * (FIN / OUTB) + jj;
        s = fmaf(g_u[j], W1[(size_t)j * FOUT + k], s);
    }
    g_op[b * FOUT + k] = s;
}

// ---- 7. finalize: out[0:512] then attention2 as 0/1 (double compare) ----
__global__ void finalize_kernel(float* __restrict__ out) {
    int idx = blockIdx.x * 256 + threadIdx.x;
    if (idx < FOUT) {
        float s = 0.f;
        #pragma unroll
        for (int b = 0; b < OUTB; b++) s += g_op[b * FOUT + idx];
        out[idx] = s;
    } else if (idx < FOUT + NROWS) {
        out[idx] = (g_scores[idx - FOUT] > g_thresh) ? 1.0f : 0.0f;
    }
}

extern "C" void kernel_launch(void* const* d_in, const int* in_sizes, int n_in,
                              void* d_out, int out_size) {
    const float* h   = (const float*)d_in[0];
    const float* adj = (const float*)d_in[1];
    const float* W   = (const float*)d_in[2];
    const float* a   = (const float*)d_in[3];
    const float* W1  = (const float*)d_in[4];
    float* out = (float*)d_out;

    prep_kernel<<<FIN, 128>>>(W, a, h);
    c1_kernel<<<1, 256>>>();
    main_kernel<<<NB, TPB>>>(adj);
    upartial_kernel<<<UP, 256>>>();
    ufinal_kernel<<<1, 256>>>();
    out_partial_kernel<<<OUTB, FOUT>>>(W1);
    finalize_kernel<<<(FOUT + NROWS + 255) / 256, 256>>>(out);
}

// round 9
// speedup vs baseline: 1.3840x; 1.3840x over previous
#include <cuda_runtime.h>
#include <math.h>
#include <float.h>

#define NROWS 32768
#define FIN   1024
#define FOUT  512

#define NB     296                 // main blocks = 148 SMs * 2 (exact single wave)
#define TPB    256
#define WARPS  8
#define MAXRPB 112                 // max rows per block (111 actual)
#define OUTB   64                  // blocks for W1 matvec partials

// ---- scratch (allocation-free: device globals) ----
__device__ __align__(16) float  g_v[FIN];          // W @ a2 (fp32, hot loop)
__device__ double g_hwa1[FIN];                     // h[j] * (W@a1)[j]
__device__ double g_c1;                            // (h@W)·a1
__device__ double g_scores[NROWS];                 // leaky_relu scores (double)
__device__ float  g_bm[NB];                        // per-block running max
__device__ double g_zp[NB];                        // per-block Z partials
__device__ __align__(16) float4 g_buT[256 * NB];   // TRANSPOSED block partials [col][b]
__device__ double g_thresh;                        // log(Z) - log(N)
__device__ __align__(16) float g_u[FIN];           // attention @ adj
__device__ float  g_op[OUTB * FOUT];               // out partials

// ==== double-float (TwoSum) helpers — all FP32 pipe ====
__device__ __forceinline__ void df_add_f(float& hi, float& lo, float b) {
    float s = hi + b;
    float v = s - hi;
    float e = (hi - (s - v)) + (b - v);
    lo += e;
    hi = s;
}
__device__ __forceinline__ void df_renorm(float& hi, float& lo) {
    float t = hi + lo;
    lo = lo - (t - hi);
    hi = t;
}
__device__ __forceinline__ void df_add_df(float& hi, float& lo, float bh, float bl) {
    float s = hi + bh;
    float v = s - hi;
    float e = (hi - (s - v)) + (bh - v);
    e += lo + bl;
    float t = s + e;
    lo = e - (t - s);
    hi = t;
}

// ---- 1. v = W@a2 (double->fp32) ; hwa1[j] = h[j]*(W@a1)[j] (double) ----
__global__ void prep_kernel(const float* __restrict__ W,
                            const float* __restrict__ a,
                            const float* __restrict__ h) {
    __shared__ double r1[128], r2[128];
    int j = blockIdx.x, t = threadIdx.x;
    const float* Wr = W + (size_t)j * FOUT;
    double d1 = 0.0, d2 = 0.0;
    #pragma unroll
    for (int k = t; k < FOUT; k += 128) {
        double w = (double)Wr[k];
        d1 += w * (double)a[k];
        d2 += w * (double)a[FOUT + k];
    }
    r1[t] = d1; r2[t] = d2;
    __syncthreads();
    for (int s = 64; s > 0; s >>= 1) {
        if (t < s) { r1[t] += r1[t + s]; r2[t] += r2[t + s]; }
        __syncthreads();
    }
    if (t == 0) {
        g_v[j]    = (float)r2[0];
        g_hwa1[j] = (double)h[j] * r1[0];
    }
}

// ---- 2. c1 = sum(hwa1) (double) ----
__global__ void c1_kernel() {
    __shared__ double red[256];
    int t = threadIdx.x;
    red[t] = g_hwa1[t] + g_hwa1[t + 256] + g_hwa1[t + 512] + g_hwa1[t + 768];
    __syncthreads();
    for (int s = 128; s > 0; s >>= 1) {
        if (t < s) red[t] += red[t + s];
        __syncthreads();
    }
    if (t == 0) g_c1 = red[0];
}

// ---- per-row work: df-precision score + fp32 max-shifted weighted accumulate ----
__device__ __forceinline__ void process_row(
    const float4* __restrict__ rv, const float4* __restrict__ sv4,
    int lane, float c1h, float c1l, float* __restrict__ acc, float& m,
    int row, int slot, double* __restrict__ s_sc)
{
    float dh = 0.f, dl = 0.f;
    #pragma unroll
    for (int c = 0; c < 8; c++) {
        float4 vv = sv4[c * 32 + lane];
        float cd = rv[c].x * vv.x;
        cd = fmaf(rv[c].y, vv.y, cd);
        cd = fmaf(rv[c].z, vv.z, cd);
        cd = fmaf(rv[c].w, vv.w, cd);
        df_add_f(dh, dl, cd);
    }
    df_renorm(dh, dl);
    #pragma unroll
    for (int off = 16; off > 0; off >>= 1) {
        float oh = __shfl_xor_sync(0xffffffffu, dh, off);
        float ol = __shfl_xor_sync(0xffffffffu, dl, off);
        df_add_df(dh, dl, oh, ol);
    }
    df_add_df(dh, dl, c1h, c1l);

    // leaky relu on the df pair (TwoProd for the 0.1 scale)
    if (dh < 0.f) {
        float ph = dh * 0.1f;
        float pl = fmaf(dh, 0.1f, -ph);
        pl = fmaf(dl, 0.1f, pl);
        float t = ph + pl;
        dl = pl - (t - ph);
        dh = t;
    }

    if (lane == 0) {
        double sc = (double)dh + (double)dl;   // only FP64 in the hot loop
        g_scores[row] = sc;
        s_sc[slot] = sc;
    }

    float sf = dh;
    if (sf > m) {                              // uniform branch, fires rarely
        float f = expf(m - sf);                // first hit: exp(-inf)=0
        #pragma unroll
        for (int i = 0; i < 32; i++) acc[i] *= f;
        m = sf;
    }
    float wt = expf(sf - m);
    #pragma unroll
    for (int c = 0; c < 8; c++) {
        acc[c * 4 + 0] = fmaf(wt, rv[c].x, acc[c * 4 + 0]);
        acc[c * 4 + 1] = fmaf(wt, rv[c].y, acc[c * 4 + 1]);
        acc[c * 4 + 2] = fmaf(wt, rv[c].z, acc[c * 4 + 2]);
        acc[c * 4 + 3] = fmaf(wt, rv[c].w, acc[c * 4 + 3]);
    }
}

// ---- 3. fused main pass over adj (double-buffered): scores + weighted sums + Z ----
__global__ __launch_bounds__(TPB, 2) void main_kernel(const float* __restrict__ adj) {
    __shared__ float4 sv4[FIN / 4];
    __shared__ float4 su4[WARPS * (FIN / 4)];
    __shared__ double s_sc[MAXRPB];
    __shared__ float s_m[WARPS], s_f[WARPS];
    __shared__ double s_zr[TPB];

    int tid  = threadIdx.x;
    int w    = tid >> 5;
    int lane = tid & 31;

    sv4[tid] = ((const float4*)g_v)[tid];
    __syncthreads();
    double c1d = g_c1;
    float c1h = (float)c1d;
    float c1l = (float)(c1d - (double)c1h);

    int start = (blockIdx.x * NROWS) / NB;
    int end   = ((blockIdx.x + 1) * NROWS) / NB;
    int len   = end - start;                    // 110 or 111
    int cnt   = (len - w + 7) / 8;              // rows for this warp (13/14)

    float acc[32];
    #pragma unroll
    for (int i = 0; i < 32; i++) acc[i] = 0.f;
    float m = -FLT_MAX;

    const int RSTRIDE = 8 * (FIN / 4);          // 8 rows in float4 units
    const float4* base = (const float4*)adj + (size_t)(start + w) * (FIN / 4) + lane;

    float4 A[8], B[8];
    #pragma unroll
    for (int c = 0; c < 8; c++) A[c] = __ldcs(&base[c * 32]);   // preload first row

    int i = 0;
    #pragma unroll 1
    for (; i + 2 <= cnt; i += 2) {
        const float4* pB = base + (size_t)(i + 1) * RSTRIDE;
        #pragma unroll
        for (int c = 0; c < 8; c++) B[c] = __ldcs(&pB[c * 32]);

        process_row(A, sv4, lane, c1h, c1l, acc, m,
                    start + w + i * 8, w + i * 8, s_sc);

        if (i + 2 < cnt) {
            const float4* pA = base + (size_t)(i + 2) * RSTRIDE;
            #pragma unroll
            for (int c = 0; c < 8; c++) A[c] = __ldcs(&pA[c * 32]);
        }

        process_row(B, sv4, lane, c1h, c1l, acc, m,
                    start + w + (i + 1) * 8, w + (i + 1) * 8, s_sc);
    }
    if (i < cnt)                                 // odd tail (A holds row i)
        process_row(A, sv4, lane, c1h, c1l, acc, m,
                    start + w + i * 8, w + i * 8, s_sc);

    if (lane == 0) s_m[w] = m;
    #pragma unroll
    for (int c = 0; c < 8; c++)
        su4[w * (FIN / 4) + c * 32 + lane] =
            make_float4(acc[c * 4], acc[c * 4 + 1], acc[c * 4 + 2], acc[c * 4 + 3]);
    __syncthreads();

    float mb = s_m[0];
    #pragma unroll
    for (int ww = 1; ww < WARPS; ww++) mb = fmaxf(mb, s_m[ww]);
    if (tid < WARPS) s_f[tid] = expf(s_m[tid] - mb);
    __syncthreads();

    float4 us = make_float4(0.f, 0.f, 0.f, 0.f);
    #pragma unroll
    for (int ww = 0; ww < WARPS; ww++) {
        float f = s_f[ww];
        float4 v = su4[ww * (FIN / 4) + tid];
        us.x = fmaf(f, v.x, us.x); us.y = fmaf(f, v.y, us.y);
        us.z = fmaf(f, v.z, us.z); us.w = fmaf(f, v.w, us.w);
    }
    g_buT[(size_t)tid * NB + blockIdx.x] = us;    // TRANSPOSED store: [col][b]
    if (tid == 0) g_bm[blockIdx.x] = mb;

    // per-block Z partial: exp(sc) with first-order double residual correction
    double zt = 0.0;
    if (tid < len) {
        double sc = s_sc[tid];
        float sf = (float)sc;
        double delta = sc - (double)sf;
        zt = (double)expf(sf) * (1.0 + delta);
    }
    s_zr[tid] = zt;
    __syncthreads();
    for (int s = 128; s > 0; s >>= 1) {
        if (tid < s) s_zr[tid] += s_zr[tid + s];
        __syncthreads();
    }
    if (tid == 0) g_zp[blockIdx.x] = s_zr[0];
}

// ---- 4. ucombine: one block per float4 column, coalesced over b; M, Z redundant ----
__global__ void ucombine_kernel() {
    __shared__ float  mred[256];
    __shared__ double zred[256];
    __shared__ float4 red[256];
    int t = threadIdx.x;
    int c = blockIdx.x;                          // float4 column 0..255

    // global max M
    float mm = g_bm[t];
    if (t + 256 < NB) mm = fmaxf(mm, g_bm[t + 256]);
    mred[t] = mm;
    __syncthreads();
    for (int s = 128; s > 0; s >>= 1) {
        if (t < s) mred[t] = fmaxf(mred[t], mred[t + s]);
        __syncthreads();
    }
    float M = mred[0];

    // global Z
    double z = g_zp[t];
    if (t + 256 < NB) z += g_zp[t + 256];
    zred[t] = z;
    __syncthreads();
    for (int s = 128; s > 0; s >>= 1) {
        if (t < s) zred[t] += zred[t + s];
        __syncthreads();
    }
    double Z = zred[0];

    // weighted column sum (coalesced: consecutive t -> consecutive b)
    const float4* colp = &g_buT[(size_t)c * NB];
    float f = expf(g_bm[t] - M);
    float4 v = colp[t];
    float4 us = make_float4(f * v.x, f * v.y, f * v.z, f * v.w);
    if (t + 256 < NB) {
        float f2 = expf(g_bm[t + 256] - M);
        float4 v2 = colp[t + 256];
        us.x = fmaf(f2, v2.x, us.x); us.y = fmaf(f2, v2.y, us.y);
        us.z = fmaf(f2, v2.z, us.z); us.w = fmaf(f2, v2.w, us.w);
    }
    red[t] = us;
    __syncthreads();
    for (int s = 128; s > 0; s >>= 1) {
        if (t < s) {
            red[t].x += red[t + s].x; red[t].y += red[t + s].y;
            red[t].z += red[t + s].z; red[t].w += red[t + s].w;
        }
        __syncthreads();
    }
    if (t == 0) {
        float sD = (float)(exp((double)M) / Z);
        float4 r = red[0];
        ((float4*)g_u)[c] = make_float4(r.x * sD, r.y * sD, r.z * sD, r.w * sD);
        if (c == 0) g_thresh = log(Z) - log((double)NROWS);
    }
}

// ---- 5. out partials: u @ W_1, j-split across 64 blocks ----
__global__ void out_partial_kernel(const float* __restrict__ W1) {
    int k = threadIdx.x;   // 0..511 coalesced over W1 columns
    int b = blockIdx.x;    // 0..63
    float s = 0.f;
    #pragma unroll
    for (int jj = 0; jj < FIN / OUTB; jj++) {
        int j = b * (FIN / OUTB) + jj;
        s = fmaf(g_u[j], W1[(size_t)j * FOUT + k], s);
    }
    g_op[b * FOUT + k] = s;
}

// ---- 6. finalize: out[0:512] then attention2 as 0/1 (double compare) ----
__global__ void finalize_kernel(float* __restrict__ out) {
    int idx = blockIdx.x * 256 + threadIdx.x;
    if (idx < FOUT) {
        float s = 0.f;
        #pragma unroll
        for (int b = 0; b < OUTB; b++) s += g_op[b * FOUT + idx];
        out[idx] = s;
    } else if (idx < FOUT + NROWS) {
        out[idx] = (g_scores[idx - FOUT] > g_thresh) ? 1.0f : 0.0f;
    }
}

extern "C" void kernel_launch(void* const* d_in, const int* in_sizes, int n_in,
                              void* d_out, int out_size) {
    const float* h   = (const float*)d_in[0];
    const float* adj = (const float*)d_in[1];
    const float* W   = (const float*)d_in[2];
    const float* a   = (const float*)d_in[3];
    const float* W1  = (const float*)d_in[4];
    float* out = (float*)d_out;

    prep_kernel<<<FIN, 128>>>(W, a, h);
    c1_kernel<<<1, 256>>>();
    main_kernel<<<NB, TPB>>>(adj);
    ucombine_kernel<<<FIN / 4, 256>>>();
    out_partial_kernel<<<OUTB, FOUT>>>(W1);
    finalize_kernel<<<(FOUT + NROWS + 255) / 256, 256>>>(out);
}